// round 7
// baseline (speedup 1.0000x reference)
#include <cuda_runtime.h>
#include <cuda_fp16.h>
#include <math.h>
#include <stdint.h>

#define N_NODES 8192
#define D 256
#define NG 8
#define ELLW 768   // max row degree bound; binomial(8192,0.05) max ~ 490

// ---------------- device scratch (no allocations allowed) ----------------
__device__ unsigned short g_cols[(size_t)N_NODES * ELLW];
__device__ __half         g_coefh[(size_t)N_NODES * ELLW];
__device__ int            g_deg[N_NODES];
__device__ float          g_X1[(size_t)N_NODES * D];
__device__ float          g_X2[(size_t)N_NODES * D];
__device__ __half2        g_h2[(size_t)N_NODES * (D / 2)];   // h = X @ W, fp16 row-major
__device__ float          g_s1[N_NODES];
__device__ float          g_s2[N_NODES];
__device__ float          g_q[N_NODES];
__device__ float          g_invZ[N_NODES];
__device__ float          g_wa[D];
__device__ float          g_wb[D];
__device__ float          g_Spart[32][D];
__device__ float          g_S[D];
__device__ float          g_mid[(size_t)N_NODES * 64];
__device__ float          g_gpart[(size_t)64 * NG * D];
__device__ int            g_gcntp[64 * NG];
__device__ float          g_gsum[NG * D];
__device__ float          g_gcnt[NG];

// ---------------- helpers ----------------
__device__ __forceinline__ float gelu_exact(float x) {
    return 0.5f * x * (1.0f + erff(x * 0.70710678118654752f));
}

__device__ __forceinline__ uint32_t smem_addr(const void* p) {
    return (uint32_t)__cvta_generic_to_shared(p);
}

__device__ __forceinline__ void ldsm_x4(uint32_t addr, uint32_t& r0, uint32_t& r1,
                                        uint32_t& r2, uint32_t& r3) {
    asm volatile("ldmatrix.sync.aligned.m8n8.x4.shared.b16 {%0,%1,%2,%3}, [%4];"
                 : "=r"(r0), "=r"(r1), "=r"(r2), "=r"(r3) : "r"(addr));
}

__device__ __forceinline__ void ldsm_x2_trans(uint32_t addr, uint32_t& r0, uint32_t& r1) {
    asm volatile("ldmatrix.sync.aligned.m8n8.x2.trans.shared.b16 {%0,%1}, [%2];"
                 : "=r"(r0), "=r"(r1) : "r"(addr));
}

__device__ __forceinline__ void mma16816(float* c, uint32_t a0, uint32_t a1, uint32_t a2,
                                         uint32_t a3, uint32_t b0, uint32_t b1) {
    asm volatile(
        "mma.sync.aligned.m16n8k16.row.col.f32.f16.f16.f32 "
        "{%0,%1,%2,%3}, {%4,%5,%6,%7}, {%8,%9}, {%0,%1,%2,%3};"
        : "+f"(c[0]), "+f"(c[1]), "+f"(c[2]), "+f"(c[3])
        : "r"(a0), "r"(a1), "r"(a2), "r"(a3), "r"(b0), "r"(b1));
}

// ---------------- 0: dense adj -> ELL (deterministic, sorted cols) ----------------
__global__ void build_ell_kernel(const float* __restrict__ adj) {
    int i = blockIdx.x;
    int tid = threadIdx.x;             // 256
    int lane = tid & 31, w = tid >> 5;
    __shared__ int wcnt[8];
    const float* row = adj + (size_t)i * N_NODES;
    int base = 0;
    for (int c0 = 0; c0 < N_NODES; c0 += 256) {
        int c = c0 + tid;
        bool pred = (row[c] != 0.0f);
        unsigned bal = __ballot_sync(0xffffffffu, pred);
        if (lane == 0) wcnt[w] = __popc(bal);
        __syncthreads();
        int off = 0, tot = 0;
#pragma unroll
        for (int k = 0; k < 8; k++) { int v = wcnt[k]; tot += v; if (k < w) off += v; }
        if (pred) {
            int pos = base + off + __popc(bal & ((1u << lane) - 1u));
            if (pos < ELLW) g_cols[(size_t)i * ELLW + pos] = (unsigned short)c;
        }
        base += tot;
        __syncthreads();
    }
    if (tid == 0) g_deg[i] = (base < ELLW) ? base : ELLW;
}

// ---------------- 1: wa = W @ a_top, wb = W @ a_bot ----------------
__global__ void wavec_kernel(const float* __restrict__ W, const float* __restrict__ a) {
    __shared__ float at[D], ab[D];
    int t = threadIdx.x; // 256
    at[t] = a[t];
    ab[t] = a[D + t];
    __syncthreads();
    float s1 = 0.0f, s2 = 0.0f;
    const float* wr = W + (size_t)t * D;
#pragma unroll 8
    for (int c = 0; c < D; c++) { float w = wr[c]; s1 += w * at[c]; s2 += w * ab[c]; }
    g_wa[t] = s1;
    g_wb[t] = s2;
}

// ---------------- 2: s1 = X @ wa, s2 = X @ wb (fp32 exact logit path) ----------------
__global__ void s12_kernel(const float* __restrict__ X) {
    int w = threadIdx.x >> 5, lane = threadIdx.x & 31;
    int i = blockIdx.x * 8 + w;
    const float* xr = X + (size_t)i * D;
    float a1 = 0.0f, a2 = 0.0f;
#pragma unroll
    for (int jj = 0; jj < 8; jj++) {
        int j = jj * 32 + lane;
        float x = xr[j];
        a1 += x * g_wa[j];
        a2 += x * g_wb[j];
    }
#pragma unroll
    for (int o = 16; o > 0; o >>= 1) {
        a1 += __shfl_down_sync(0xffffffffu, a1, o);
        a2 += __shfl_down_sync(0xffffffffu, a2, o);
    }
    if (lane == 0) { g_s1[i] = a1; g_s2[i] = a2; }
}

// ---------------- 3: fp32 GEMM C = act(A@B + bias). BM=128,BN=64, 8x4 microtile ----------------
template <int ACT, int OUTH>
__global__ __launch_bounds__(256) void gemm_kernel(const float* __restrict__ A,
                                                   const float* __restrict__ B,
                                                   const float* __restrict__ bias,
                                                   void* __restrict__ C,
                                                   int M, int N, int K) {
    const int BM = 128, BN = 64, BK = 16;
    __shared__ __align__(16) float As[BK][BM];
    __shared__ __align__(16) float Bs[BK][BN];
    int tid = threadIdx.x;  // 256
    int m0 = blockIdx.y * BM, n0 = blockIdx.x * BN;
    int tx = tid & 15, ty = tid >> 4;
    float acc[8][4];
#pragma unroll
    for (int i = 0; i < 8; i++)
#pragma unroll
        for (int j = 0; j < 4; j++) acc[i][j] = 0.0f;

    int ar = tid >> 1;
    int ac = (tid & 1) * 8;
    int br = tid >> 4;
    int bc = (tid & 15) * 4;

    for (int k0 = 0; k0 < K; k0 += BK) {
        {
            const float* ap = &A[(size_t)(m0 + ar) * K + k0 + ac];
            float4 v0 = *reinterpret_cast<const float4*>(ap);
            float4 v1 = *reinterpret_cast<const float4*>(ap + 4);
            As[ac + 0][ar] = v0.x; As[ac + 1][ar] = v0.y;
            As[ac + 2][ar] = v0.z; As[ac + 3][ar] = v0.w;
            As[ac + 4][ar] = v1.x; As[ac + 5][ar] = v1.y;
            As[ac + 6][ar] = v1.z; As[ac + 7][ar] = v1.w;
        }
        {
            float4 v = *reinterpret_cast<const float4*>(&B[(size_t)(k0 + br) * N + n0 + bc]);
            *reinterpret_cast<float4*>(&Bs[br][bc]) = v;
        }
        __syncthreads();
#pragma unroll
        for (int kk = 0; kk < BK; kk++) {
            float4 a0 = *reinterpret_cast<const float4*>(&As[kk][ty * 8]);
            float4 a1 = *reinterpret_cast<const float4*>(&As[kk][ty * 8 + 4]);
            float4 bv = *reinterpret_cast<const float4*>(&Bs[kk][tx * 4]);
            float a8[8] = {a0.x, a0.y, a0.z, a0.w, a1.x, a1.y, a1.z, a1.w};
            float b4[4] = {bv.x, bv.y, bv.z, bv.w};
#pragma unroll
            for (int i = 0; i < 8; i++)
#pragma unroll
                for (int j = 0; j < 4; j++) acc[i][j] += a8[i] * b4[j];
        }
        __syncthreads();
    }
#pragma unroll
    for (int i = 0; i < 8; i++)
#pragma unroll
        for (int j = 0; j < 4; j++) {
            int r = m0 + ty * 8 + i, c = n0 + tx * 4 + j;
            float v = acc[i][j];
            if (ACT == 1) { v += bias[c]; v = gelu_exact(v); }
            if (OUTH) ((__half*)C)[(size_t)r * N + c] = __float2half(v);
            else      ((float*)C)[(size_t)r * N + c] = v;
        }
}

// ---------------- 4: column sum of h ----------------
__global__ void colsum_part_kernel() {
    int d = threadIdx.x, b = blockIdx.x;  // 32 blocks
    const __half* h = reinterpret_cast<const __half*>(g_h2);
    float s = 0.0f;
    int r0 = b * (N_NODES / 32);
    for (int r = r0; r < r0 + (N_NODES / 32); r++) s += __half2float(h[(size_t)r * D + d]);
    g_Spart[b][d] = s;
}
__global__ void colsum_red_kernel() {
    int d = threadIdx.x;
    float s = 0.0f;
#pragma unroll
    for (int b = 0; b < 32; b++) s += g_Spart[b][d];
    g_S[d] = s;
}

// ---------------- 5a: per-row softmax constants + fp16 edge coefficients ----------------
__global__ __launch_bounds__(256) void coef_kernel() {
    int wid = threadIdx.x >> 5, lane = threadIdx.x & 31;
    int i = blockIdx.x * 8 + wid;
    int deg = g_deg[i];
    float s1 = g_s1[i];
    const unsigned short* __restrict__ crow = g_cols + (size_t)i * ELLW;
    __half* __restrict__ cfrow = g_coefh + (size_t)i * ELLW;

    float tmax = -1e30f;
    for (int k = lane; k < deg; k += 32) tmax = fmaxf(tmax, g_s2[crow[k]]);
#pragma unroll
    for (int o = 16; o > 0; o >>= 1) tmax = fmaxf(tmax, __shfl_xor_sync(0xffffffffu, tmax, o));

    float m;
    {
        float z = s1 + tmax;
        float lr = (z > 0.0f) ? z : 0.2f * z;
        m = fmaxf(lr, 0.0f);
        if (deg == 0) m = 0.0f;
    }
    float q = __expf(-m);

    float zs = 0.0f;
    for (int k = lane; k < deg; k += 32) {
        float z = s1 + g_s2[crow[k]];
        float lr = (z > 0.0f) ? z : 0.2f * z;
        float p = __expf(lr - m);
        zs += p;
        cfrow[k] = __float2half(p - q);
    }
#pragma unroll
    for (int o = 16; o > 0; o >>= 1) zs += __shfl_xor_sync(0xffffffffu, zs, o);

    if (lane == 0) {
        float Z = zs + (float)(N_NODES - deg) * q;
        g_q[i] = q;
        g_invZ[i] = 1.0f / Z;
    }
}

// ---------------- 5b: tiled tensor-core aggregation + epilogue ----------------
// grid: 128 blocks (64-row tiles), 512 threads (16 warps: 4 m-tiles x 4 n-tiles)
// smem: As[64][136] half (17408 B) | Bs[4][128][72] half (73728 B, aliased by Cs[64][260] f32)
#define SM_AS_BYTES 17408
#define SM_TOTAL_BYTES (17408 + 73728)

__global__ __launch_bounds__(512) void gat_tile_kernel(const float* __restrict__ Xin,
                                                       const float* __restrict__ lng,
                                                       const float* __restrict__ lnb,
                                                       float* __restrict__ Xout,
                                                       int residual) {
    extern __shared__ __align__(16) char smem[];
    __half* As = reinterpret_cast<__half*>(smem);                    // [64][136]
    __half* Bs = reinterpret_cast<__half*>(smem + SM_AS_BYTES);      // [4][128][72]
    float*  Cs = reinterpret_cast<float*>(smem + SM_AS_BYTES);       // alias [64][260]

    const int tid = threadIdx.x;
    const int wid = tid >> 5, lane = tid & 31;
    const int wm = wid >> 2, wn = wid & 3;
    const int tile = blockIdx.x;
    const int r0g = tile * 64;

    // scatter state (threads 0..63 own one row each)
    int deg = 0, cur = 0, cnext = 0x7fffffff;
    const unsigned short* crow = nullptr;
    const __half* cfrow = nullptr;
    if (tid < 64) {
        int i = r0g + tid;
        deg = g_deg[i];
        crow = g_cols + (size_t)i * ELLW;
        cfrow = g_coefh + (size_t)i * ELLW;
        cnext = (deg > 0) ? (int)crow[0] : 0x7fffffff;
    }

    // mma fragment base addresses
    const uint32_t as_frag = smem_addr(As) + (uint32_t)((wm * 16 + (lane & 15)) * 272 + (lane >> 4) * 16);
    const uint32_t bs_frag = smem_addr(Bs) + (uint32_t)(wn * 128 * 144 + (lane & 15) * 144);

    // B-tile load mapping: thread -> (row bj, quarter bq); rotated chunks for bank-free stores
    const int bj = tid >> 2, bq = tid & 3;
    const uint4* __restrict__ hsrc = reinterpret_cast<const uint4*>(g_h2);  // 32 uint4 per node row

    float acc[8][4];
#pragma unroll
    for (int i = 0; i < 8; i++)
#pragma unroll
        for (int j = 0; j < 4; j++) acc[i][j] = 0.0f;

    for (int jt = 0; jt < 64; jt++) {
        __syncthreads();   // previous mma done reading tiles
        // zero A tile (1088 uint4)
        uint4 zz; zz.x = 0; zz.y = 0; zz.z = 0; zz.w = 0;
        for (int z0 = tid; z0 < 1088; z0 += 512) reinterpret_cast<uint4*>(As)[z0] = zz;
        // load B tile: h rows [jt*128, jt*128+128), seg bq holds d-range [bq*64,(bq+1)*64)
        {
            const uint4* src = hsrc + (size_t)(jt * 128 + bj) * 32;
            uint4* dstrow = reinterpret_cast<uint4*>(Bs + (size_t)bq * 128 * 72 + (size_t)bj * 72);
#pragma unroll
            for (int ii = 0; ii < 8; ii++) {
                int c = (2 * bq + ii) & 7;
                dstrow[c] = src[bq * 8 + c];
            }
        }
        __syncthreads();
        // scatter edge coefs of this col range into A tile
        if (tid < 64) {
            int climit = (jt << 7) + 128;
            while (cnext < climit) {
                As[tid * 136 + (cnext - (jt << 7))] = cfrow[cur];
                cur++;
                cnext = (cur < deg) ? (int)crow[cur] : 0x7fffffff;
            }
        }
        __syncthreads();
        // mma accumulate: C[64x256] += A[64x128] @ B[128x256]
#pragma unroll
        for (int k8 = 0; k8 < 8; k8++) {
            uint32_t a0, a1, a2, a3;
            ldsm_x4(as_frag + k8 * 32, a0, a1, a2, a3);
#pragma unroll
            for (int nb = 0; nb < 8; nb++) {
                uint32_t b0, b1;
                ldsm_x2_trans(bs_frag + k8 * 16 * 144 + nb * 16, b0, b1);
                mma16816(acc[nb], a0, a1, a2, a3, b0, b1);
            }
        }
    }
    __syncthreads();  // all mma done; Cs may alias Bs now

    // store fragments to Cs
    {
        int fr = wm * 16 + (lane >> 2);
        int fc = wn * 64 + (lane & 3) * 2;
#pragma unroll
        for (int nb = 0; nb < 8; nb++) {
            int c0 = fc + nb * 8;
            Cs[fr * 260 + c0] = acc[nb][0];
            Cs[fr * 260 + c0 + 1] = acc[nb][1];
            Cs[(fr + 8) * 260 + c0] = acc[nb][2];
            Cs[(fr + 8) * 260 + c0 + 1] = acc[nb][3];
        }
    }
    __syncthreads();

    // epilogue: 8 threads per row; each handles 32 cols
    {
        const int er = tid >> 3, es = tid & 7;
        const int gi = r0g + er;
        const float q = g_q[gi];
        const float invZ = g_invZ[gi];
        float vals[32];
        float sum = 0.0f;
#pragma unroll
        for (int c = 0; c < 32; c++) {
            int cc = es * 32 + c;
            float v = (Cs[er * 260 + cc] + q * g_S[cc]) * invZ;
            v = (v > 0.0f) ? v : expm1f(v);
            vals[c] = v;
            sum += v;
        }
#pragma unroll
        for (int o = 1; o < 8; o <<= 1) sum += __shfl_xor_sync(0xffffffffu, sum, o);
        float mean = sum * (1.0f / 256.0f);
        float sq = 0.0f;
#pragma unroll
        for (int c = 0; c < 32; c++) { float dd = vals[c] - mean; sq += dd * dd; }
#pragma unroll
        for (int o = 1; o < 8; o <<= 1) sq += __shfl_xor_sync(0xffffffffu, sq, o);
        float rstd = rsqrtf(sq * (1.0f / 256.0f) + 1e-5f);
#pragma unroll
        for (int c = 0; c < 32; c++) {
            int cc = es * 32 + c;
            float y = (vals[c] - mean) * rstd * lng[cc] + lnb[cc];
            if (residual) y += Xin[(size_t)gi * D + cc];
            Xout[(size_t)gi * D + cc] = y;
        }
    }
}

// ---------------- 6: node logits (8192x64)@(64x5)+b ----------------
__global__ void node_logits_kernel(const float* __restrict__ mid, const float* __restrict__ w2,
                                   const float* __restrict__ b2, float* __restrict__ out) {
    int i = blockIdx.x, t = threadIdx.x;  // 64
    __shared__ float sm[64];
    sm[t] = mid[(size_t)i * 64 + t];
    __syncthreads();
    if (t < 5) {
        float s = b2[t];
#pragma unroll 8
        for (int k = 0; k < 64; k++) s += sm[k] * w2[k * 5 + t];
        out[(size_t)i * 5 + t] = s;
    }
}

// ---------------- 7: deterministic segment pooling ----------------
__global__ void pool_part_kernel(const float* __restrict__ h3, const int* __restrict__ mask) {
    __shared__ float sacc[NG * D];
    int d = threadIdx.x;  // 256
    int b = blockIdx.x;   // 64 blocks x 128 rows
#pragma unroll
    for (int g = 0; g < NG; g++) sacc[g * D + d] = 0.0f;
    __syncthreads();
    int r0 = b * 128, lc = 0;
    for (int r = r0; r < r0 + 128; r++) {
        int g = mask[r];
        sacc[g * D + d] += h3[(size_t)r * D + d];
        if (d < NG && g == d) lc++;
    }
    __syncthreads();
#pragma unroll
    for (int g = 0; g < NG; g++)
        g_gpart[((size_t)b * NG + g) * D + d] = sacc[g * D + d];
    if (d < NG) g_gcntp[b * NG + d] = lc;
}
__global__ void pool_red_kernel() {
    int g = blockIdx.x, d = threadIdx.x;  // 8 x 256
    float s = 0.0f;
    for (int b = 0; b < 64; b++) s += g_gpart[((size_t)b * NG + g) * D + d];
    g_gsum[g * D + d] = s;
    if (d == 0) {
        int c = 0;
        for (int b = 0; b < 64; b++) c += g_gcntp[b * NG + g];
        g_gcnt[g] = (float)c;
    }
}

// ---------------- 8: graph heads ----------------
__global__ void graph_head_kernel(const float* __restrict__ gc_w1, const float* __restrict__ gc_b1,
                                  const float* __restrict__ gc_w2, const float* __restrict__ gc_b2,
                                  const float* __restrict__ rs_w1, const float* __restrict__ rs_b1,
                                  const float* __restrict__ rs_w2, const float* __restrict__ rs_b2,
                                  float* __restrict__ graph_logits, float* __restrict__ risk) {
    __shared__ float ge[D];
    __shared__ float hid[64];
    __shared__ float hid2[32];
    int d = threadIdx.x;  // 256
    for (int g = 0; g < NG; g++) {
        float cnt = fmaxf(g_gcnt[g], 1.0f);
        ge[d] = g_gsum[g * D + d] / cnt;
        __syncthreads();
        if (d < 64) {
            float s = gc_b1[d];
            for (int k = 0; k < D; k++) s += ge[k] * gc_w1[k * 64 + d];
            hid[d] = gelu_exact(s);
        } else if (d < 96) {
            int t = d - 64;
            float s = rs_b1[t];
            for (int k = 0; k < D; k++) s += ge[k] * rs_w1[k * 32 + t];
            hid2[t] = gelu_exact(s);
        }
        __syncthreads();
        if (d < 3) {
            float s = gc_b2[d];
            for (int k = 0; k < 64; k++) s += hid[k] * gc_w2[k * 3 + d];
            graph_logits[g * 3 + d] = s;
        }
        if (d == 3) {
            float s = rs_b2[0];
            for (int k = 0; k < 32; k++) s += hid2[k] * rs_w2[k];
            risk[g] = 1.0f / (1.0f + expf(-s));
        }
        __syncthreads();
    }
}

// ---------------- launch ----------------
extern "C" void kernel_launch(void* const* d_in, const int* in_sizes, int n_in,
                              void* d_out, int out_size) {
    const float* x    = (const float*)d_in[0];
    const float* adj  = (const float*)d_in[1];
    const int*   mask = (const int*)d_in[2];
    const float* W[3]   = {(const float*)d_in[3], (const float*)d_in[5], (const float*)d_in[7]};
    const float* a[3]   = {(const float*)d_in[4], (const float*)d_in[6], (const float*)d_in[8]};
    const float* lng[3] = {(const float*)d_in[9],  (const float*)d_in[11], (const float*)d_in[13]};
    const float* lnb[3] = {(const float*)d_in[10], (const float*)d_in[12], (const float*)d_in[14]};
    const float* nc_w1 = (const float*)d_in[15];
    const float* nc_b1 = (const float*)d_in[16];
    const float* nc_w2 = (const float*)d_in[17];
    const float* nc_b2 = (const float*)d_in[18];
    const float* gc_w1 = (const float*)d_in[19];
    const float* gc_b1 = (const float*)d_in[20];
    const float* gc_w2 = (const float*)d_in[21];
    const float* gc_b2 = (const float*)d_in[22];
    const float* rs_w1 = (const float*)d_in[23];
    const float* rs_b1 = (const float*)d_in[24];
    const float* rs_w2 = (const float*)d_in[25];
    const float* rs_b2 = (const float*)d_in[26];

    float* out = (float*)d_out;
    float* out_node  = out;                 // 8192*5
    float* out_graph = out + 40960;         // 8*3
    float* out_risk  = out + 40984;         // 8
    float* out_h3    = out + 40992;         // 8192*256

    // resolve device-global scratch addresses
    float *pX1, *pX2; void* ph;
    cudaGetSymbolAddress((void**)&pX1, g_X1);
    cudaGetSymbolAddress((void**)&pX2, g_X2);
    cudaGetSymbolAddress(&ph, g_h2);
    float* pmid; cudaGetSymbolAddress((void**)&pmid, g_mid);

    cudaFuncSetAttribute(gat_tile_kernel, cudaFuncAttributeMaxDynamicSharedMemorySize,
                         SM_TOTAL_BYTES);

    build_ell_kernel<<<N_NODES, 256>>>(adj);

    const float* Xprev = x;
    float* Xouts[3] = {pX1, pX2, out_h3};
    for (int L = 0; L < 3; L++) {
        wavec_kernel<<<1, 256>>>(W[L], a[L]);
        s12_kernel<<<N_NODES / 8, 256>>>(Xprev);
        gemm_kernel<0, 1><<<dim3(D / 64, N_NODES / 128), 256>>>(Xprev, W[L], nullptr, ph,
                                                                N_NODES, D, D);
        colsum_part_kernel<<<32, 256>>>();
        colsum_red_kernel<<<1, 256>>>();
        coef_kernel<<<N_NODES / 8, 256>>>();
        gat_tile_kernel<<<128, 512, SM_TOTAL_BYTES>>>(Xprev, lng[L], lnb[L], Xouts[L],
                                                      L > 0 ? 1 : 0);
        Xprev = Xouts[L];
    }

    // node head: mid = gelu(h3 @ nc_w1 + b1); logits = mid @ nc_w2 + b2
    gemm_kernel<1, 0><<<dim3(1, N_NODES / 128), 256>>>(out_h3, nc_w1, nc_b1, pmid,
                                                       N_NODES, 64, D);
    node_logits_kernel<<<N_NODES, 64>>>(pmid, nc_w2, nc_b2, out_node);

    // graph heads
    pool_part_kernel<<<64, 256>>>(out_h3, mask);
    pool_red_kernel<<<NG, 256>>>();
    graph_head_kernel<<<1, 256>>>(gc_w1, gc_b1, gc_w2, gc_b2,
                                  rs_w1, rs_b1, rs_w2, rs_b2,
                                  out_graph, out_risk);
}

// round 9
// speedup vs baseline: 1.0202x; 1.0202x over previous
#include <cuda_runtime.h>
#include <cuda_fp16.h>
#include <math.h>
#include <stdint.h>

#define N_NODES 8192
#define D 256
#define NG 8
#define ELLW 768   // max row degree bound; binomial(8192,0.05) max ~ 490

// ---------------- device scratch (no allocations allowed) ----------------
__device__ unsigned short g_cols[(size_t)N_NODES * ELLW];
__device__ __half         g_coefh[(size_t)N_NODES * ELLW];
__device__ int            g_jtstart[(size_t)N_NODES * 65];   // CSR offsets per 128-col tile
__device__ int            g_deg[N_NODES];
__device__ float          g_X1[(size_t)N_NODES * D];
__device__ float          g_X2[(size_t)N_NODES * D];
__device__ __half2        g_h2[(size_t)N_NODES * (D / 2)];   // h = X @ W, fp16 row-major
__device__ float          g_s1[N_NODES];
__device__ float          g_s2[N_NODES];
__device__ float          g_q[N_NODES];
__device__ float          g_invZ[N_NODES];
__device__ float          g_wa[D];
__device__ float          g_wb[D];
__device__ float          g_Spart[32][D];
__device__ float          g_S[D];
__device__ float          g_mid[(size_t)N_NODES * 64];
__device__ float          g_gpart[(size_t)64 * NG * D];
__device__ int            g_gcntp[64 * NG];
__device__ float          g_gsum[NG * D];
__device__ float          g_gcnt[NG];

// ---------------- helpers ----------------
__device__ __forceinline__ float gelu_exact(float x) {
    return 0.5f * x * (1.0f + erff(x * 0.70710678118654752f));
}

__device__ __forceinline__ uint32_t smem_addr(const void* p) {
    return (uint32_t)__cvta_generic_to_shared(p);
}

__device__ __forceinline__ void cp_async16(uint32_t dst, const void* src) {
    asm volatile("cp.async.cg.shared.global [%0], [%1], 16;" :: "r"(dst), "l"(src));
}
__device__ __forceinline__ void cp_commit() {
    asm volatile("cp.async.commit_group;");
}
__device__ __forceinline__ void cp_wait1() {
    asm volatile("cp.async.wait_group 1;");
}
__device__ __forceinline__ void cp_wait0() {
    asm volatile("cp.async.wait_group 0;");
}

__device__ __forceinline__ void ldsm_x4(uint32_t addr, uint32_t& r0, uint32_t& r1,
                                        uint32_t& r2, uint32_t& r3) {
    asm volatile("ldmatrix.sync.aligned.m8n8.x4.shared.b16 {%0,%1,%2,%3}, [%4];"
                 : "=r"(r0), "=r"(r1), "=r"(r2), "=r"(r3) : "r"(addr));
}

__device__ __forceinline__ void ldsm_x2_trans(uint32_t addr, uint32_t& r0, uint32_t& r1) {
    asm volatile("ldmatrix.sync.aligned.m8n8.x2.trans.shared.b16 {%0,%1}, [%2];"
                 : "=r"(r0), "=r"(r1) : "r"(addr));
}

__device__ __forceinline__ void mma16816(float* c, uint32_t a0, uint32_t a1, uint32_t a2,
                                         uint32_t a3, uint32_t b0, uint32_t b1) {
    asm volatile(
        "mma.sync.aligned.m16n8k16.row.col.f32.f16.f16.f32 "
        "{%0,%1,%2,%3}, {%4,%5,%6,%7}, {%8,%9}, {%0,%1,%2,%3};"
        : "+f"(c[0]), "+f"(c[1]), "+f"(c[2]), "+f"(c[3])
        : "r"(a0), "r"(a1), "r"(a2), "r"(a3), "r"(b0), "r"(b1));
}

// ---------------- 0: dense adj -> ELL (deterministic, sorted cols) ----------------
__global__ void build_ell_kernel(const float* __restrict__ adj) {
    int i = blockIdx.x;
    int tid = threadIdx.x;             // 256
    int lane = tid & 31, w = tid >> 5;
    __shared__ int wcnt[8];
    const float* row = adj + (size_t)i * N_NODES;
    int base = 0;
    for (int c0 = 0; c0 < N_NODES; c0 += 256) {
        int c = c0 + tid;
        bool pred = (row[c] != 0.0f);
        unsigned bal = __ballot_sync(0xffffffffu, pred);
        if (lane == 0) wcnt[w] = __popc(bal);
        __syncthreads();
        int off = 0, tot = 0;
#pragma unroll
        for (int k = 0; k < 8; k++) { int v = wcnt[k]; tot += v; if (k < w) off += v; }
        if (pred) {
            int pos = base + off + __popc(bal & ((1u << lane) - 1u));
            if (pos < ELLW) g_cols[(size_t)i * ELLW + pos] = (unsigned short)c;
        }
        base += tot;
        __syncthreads();
    }
    if (tid == 0) g_deg[i] = (base < ELLW) ? base : ELLW;
}

// ---------------- 1: wa = W @ a_top, wb = W @ a_bot ----------------
__global__ void wavec_kernel(const float* __restrict__ W, const float* __restrict__ a) {
    __shared__ float at[D], ab[D];
    int t = threadIdx.x; // 256
    at[t] = a[t];
    ab[t] = a[D + t];
    __syncthreads();
    float s1 = 0.0f, s2 = 0.0f;
    const float* wr = W + (size_t)t * D;
#pragma unroll 8
    for (int c = 0; c < D; c++) { float w = wr[c]; s1 += w * at[c]; s2 += w * ab[c]; }
    g_wa[t] = s1;
    g_wb[t] = s2;
}

// ---------------- 2: s1 = X @ wa, s2 = X @ wb (fp32 exact logit path) ----------------
__global__ void s12_kernel(const float* __restrict__ X) {
    int w = threadIdx.x >> 5, lane = threadIdx.x & 31;
    int i = blockIdx.x * 8 + w;
    const float* xr = X + (size_t)i * D;
    float a1 = 0.0f, a2 = 0.0f;
#pragma unroll
    for (int jj = 0; jj < 8; jj++) {
        int j = jj * 32 + lane;
        float x = xr[j];
        a1 += x * g_wa[j];
        a2 += x * g_wb[j];
    }
#pragma unroll
    for (int o = 16; o > 0; o >>= 1) {
        a1 += __shfl_down_sync(0xffffffffu, a1, o);
        a2 += __shfl_down_sync(0xffffffffu, a2, o);
    }
    if (lane == 0) { g_s1[i] = a1; g_s2[i] = a2; }
}

// ---------------- 3: fp32 GEMM C = act(A@B + bias). BM=128,BN=64, 8x4 microtile ----------------
template <int ACT, int OUTH>
__global__ __launch_bounds__(256) void gemm_kernel(const float* __restrict__ A,
                                                   const float* __restrict__ B,
                                                   const float* __restrict__ bias,
                                                   void* __restrict__ C,
                                                   int M, int N, int K) {
    const int BM = 128, BN = 64, BK = 16;
    __shared__ __align__(16) float As[BK][BM];
    __shared__ __align__(16) float Bs[BK][BN];
    int tid = threadIdx.x;  // 256
    int m0 = blockIdx.y * BM, n0 = blockIdx.x * BN;
    int tx = tid & 15, ty = tid >> 4;
    float acc[8][4];
#pragma unroll
    for (int i = 0; i < 8; i++)
#pragma unroll
        for (int j = 0; j < 4; j++) acc[i][j] = 0.0f;

    int ar = tid >> 1;
    int ac = (tid & 1) * 8;
    int br = tid >> 4;
    int bc = (tid & 15) * 4;

    for (int k0 = 0; k0 < K; k0 += BK) {
        {
            const float* ap = &A[(size_t)(m0 + ar) * K + k0 + ac];
            float4 v0 = *reinterpret_cast<const float4*>(ap);
            float4 v1 = *reinterpret_cast<const float4*>(ap + 4);
            As[ac + 0][ar] = v0.x; As[ac + 1][ar] = v0.y;
            As[ac + 2][ar] = v0.z; As[ac + 3][ar] = v0.w;
            As[ac + 4][ar] = v1.x; As[ac + 5][ar] = v1.y;
            As[ac + 6][ar] = v1.z; As[ac + 7][ar] = v1.w;
        }
        {
            float4 v = *reinterpret_cast<const float4*>(&B[(size_t)(k0 + br) * N + n0 + bc]);
            *reinterpret_cast<float4*>(&Bs[br][bc]) = v;
        }
        __syncthreads();
#pragma unroll
        for (int kk = 0; kk < BK; kk++) {
            float4 a0 = *reinterpret_cast<const float4*>(&As[kk][ty * 8]);
            float4 a1 = *reinterpret_cast<const float4*>(&As[kk][ty * 8 + 4]);
            float4 bv = *reinterpret_cast<const float4*>(&Bs[kk][tx * 4]);
            float a8[8] = {a0.x, a0.y, a0.z, a0.w, a1.x, a1.y, a1.z, a1.w};
            float b4[4] = {bv.x, bv.y, bv.z, bv.w};
#pragma unroll
            for (int i = 0; i < 8; i++)
#pragma unroll
                for (int j = 0; j < 4; j++) acc[i][j] += a8[i] * b4[j];
        }
        __syncthreads();
    }
#pragma unroll
    for (int i = 0; i < 8; i++)
#pragma unroll
        for (int j = 0; j < 4; j++) {
            int r = m0 + ty * 8 + i, c = n0 + tx * 4 + j;
            float v = acc[i][j];
            if (ACT == 1) { v += bias[c]; v = gelu_exact(v); }
            if (OUTH) ((__half*)C)[(size_t)r * N + c] = __float2half(v);
            else      ((float*)C)[(size_t)r * N + c] = v;
        }
}

// ---------------- 4: column sum of h ----------------
__global__ void colsum_part_kernel() {
    int d = threadIdx.x, b = blockIdx.x;  // 32 blocks
    const __half* h = reinterpret_cast<const __half*>(g_h2);
    float s = 0.0f;
    int r0 = b * (N_NODES / 32);
    for (int r = r0; r < r0 + (N_NODES / 32); r++) s += __half2float(h[(size_t)r * D + d]);
    g_Spart[b][d] = s;
}
__global__ void colsum_red_kernel() {
    int d = threadIdx.x;
    float s = 0.0f;
#pragma unroll
    for (int b = 0; b < 32; b++) s += g_Spart[b][d];
    g_S[d] = s;
}

// ---------------- 5a: softmax constants + fp16 coefs + per-tile CSR offsets ----------------
__global__ __launch_bounds__(256) void coef_kernel() {
    int wid = threadIdx.x >> 5, lane = threadIdx.x & 31;
    int i = blockIdx.x * 8 + wid;
    int deg = g_deg[i];
    float s1 = g_s1[i];
    const unsigned short* __restrict__ crow = g_cols + (size_t)i * ELLW;
    __half* __restrict__ cfrow = g_coefh + (size_t)i * ELLW;
    int* __restrict__ jts = g_jtstart + (size_t)i * 65;

    float tmax = -1e30f;
    for (int k = lane; k < deg; k += 32) tmax = fmaxf(tmax, g_s2[crow[k]]);
#pragma unroll
    for (int o = 16; o > 0; o >>= 1) tmax = fmaxf(tmax, __shfl_xor_sync(0xffffffffu, tmax, o));

    float m;
    {
        float z = s1 + tmax;
        float lr = (z > 0.0f) ? z : 0.2f * z;
        m = fmaxf(lr, 0.0f);
        if (deg == 0) m = 0.0f;
    }
    float q = __expf(-m);

    float zs = 0.0f;
    for (int k = lane; k < deg; k += 32) {
        int c = (int)crow[k];
        float z = s1 + g_s2[c];
        float lr = (z > 0.0f) ? z : 0.2f * z;
        float p = __expf(lr - m);
        zs += p;
        cfrow[k] = __float2half(p - q);
        // fill per-128-col-tile start offsets (each t written by exactly one k)
        int jtc = c >> 7;
        int prev = (k == 0) ? -1 : ((int)crow[k - 1] >> 7);
        for (int t = prev + 1; t <= jtc; t++) jts[t] = k;
        if (k == deg - 1)
            for (int t = jtc + 1; t <= 64; t++) jts[t] = deg;
    }
    if (deg == 0 && lane == 0)
        for (int t = 0; t <= 64; t++) jts[t] = 0;
#pragma unroll
    for (int o = 16; o > 0; o >>= 1) zs += __shfl_xor_sync(0xffffffffu, zs, o);

    if (lane == 0) {
        float Z = zs + (float)(N_NODES - deg) * q;
        g_q[i] = q;
        g_invZ[i] = 1.0f / Z;
    }
}

// ---------------- 5b: pipelined tensor-core aggregation + epilogue ----------------
// grid: 128 blocks (64-row tiles), 512 threads (16 warps: 4 m x 4 n)
// smem: A[2][64][136]h (2x17408) | B[2][4][128][72]h (2x73728); Cs[64][260]f aliases B
#define AS_BUF_BYTES 17408
#define BS_BUF_BYTES 73728
#define SM_TOTAL_BYTES (2 * AS_BUF_BYTES + 2 * BS_BUF_BYTES)   // 182272

__global__ __launch_bounds__(512) void gat_tile_kernel(const float* __restrict__ Xin,
                                                       const float* __restrict__ lng,
                                                       const float* __restrict__ lnb,
                                                       float* __restrict__ Xout,
                                                       int residual) {
    extern __shared__ __align__(16) char smem[];
    char* Bbase = smem + 2 * AS_BUF_BYTES;
    float* Cs = reinterpret_cast<float*>(Bbase);     // alias over B buffers

    const int tid = threadIdx.x;
    const int wid = tid >> 5, lane = tid & 31;
    const int wm = wid >> 2, wn = wid & 3;
    const int r0g = blockIdx.x * 64;

    // scatter ownership: thread (sr, ss) owns row sr, col slice [ss*16,(ss+1)*16)
    const int sr = tid >> 3, ss = tid & 7;
    const int gsr = r0g + sr;
    const int* __restrict__ jts = g_jtstart + (size_t)gsr * 65;
    const unsigned short* __restrict__ crow = g_cols + (size_t)gsr * ELLW;
    const __half* __restrict__ cfrow = g_coefh + (size_t)gsr * ELLW;

    // B cp.async mapping: thread -> (row bj 0..127, quarter bq 0..3), 8x16B chunks
    const int bj = tid >> 2, bq = tid & 3;
    const char* __restrict__ hbase = reinterpret_cast<const char*>(g_h2);

    const uint32_t as_smem = smem_addr(smem);
    const uint32_t bs_smem = smem_addr(Bbase);
    const uint32_t as_frag_off = (uint32_t)((wm * 16 + (lane & 15)) * 272 + (lane >> 4) * 16);
    const uint32_t bs_frag_off = (uint32_t)(wn * 18432 + (lane & 15) * 144);

    float acc[8][4];
#pragma unroll
    for (int i = 0; i < 8; i++)
#pragma unroll
        for (int j = 0; j < 4; j++) acc[i][j] = 0.0f;

    // zero+scatter A[buf] for col-tile jtn (each thread touches only its own slice)
    auto prepA = [&](int buf, int jtn) {
        uint4 zz; zz.x = 0; zz.y = 0; zz.z = 0; zz.w = 0;
        uint4* arow = reinterpret_cast<uint4*>(smem + buf * AS_BUF_BYTES + sr * 272);
        arow[ss * 2] = zz;
        arow[ss * 2 + 1] = zz;
        if (ss == 7) arow[16] = zz;   // pad halves [128,136)
        __half* adst = reinterpret_cast<__half*>(smem + buf * AS_BUF_BYTES) + sr * 136;
        int lo = jts[jtn], hi = jts[jtn + 1];
        int cbase = jtn << 7;
        for (int k = lo; k < hi; k++) {
            int c = (int)crow[k] - cbase;
            if ((c >> 4) == ss) adst[c] = cfrow[k];
        }
    };
    auto loadB = [&](int buf, int jt) {
        uint32_t dst = bs_smem + buf * BS_BUF_BYTES + bq * 18432 + bj * 144;
        const char* src = hbase + (size_t)(jt * 128 + bj) * 512 + bq * 128;
#pragma unroll
        for (int c = 0; c < 8; c++) cp_async16(dst + c * 16, src + c * 16);
    };

    // prologue: stage tile 0
    prepA(0, 0);
    loadB(0, 0);
    cp_commit();

    for (int jt = 0; jt < 64; jt++) {
        const int buf = jt & 1;
        __syncthreads();   // mma of jt-1 done reading A/B[buf^1]; A[buf] scatter published
        if (jt < 63) {
            prepA(buf ^ 1, jt + 1);
            loadB(buf ^ 1, jt + 1);
            cp_commit();
            cp_wait1();    // B[jt] complete
        } else {
            cp_wait0();
        }
        __syncthreads();   // B[jt] visible block-wide
        const uint32_t as_frag = as_smem + buf * AS_BUF_BYTES + as_frag_off;
        const uint32_t bs_frag = bs_smem + buf * BS_BUF_BYTES + bs_frag_off;
#pragma unroll
        for (int k8 = 0; k8 < 8; k8++) {
            uint32_t a0, a1, a2, a3;
            ldsm_x4(as_frag + k8 * 32, a0, a1, a2, a3);
#pragma unroll
            for (int nb = 0; nb < 8; nb++) {
                uint32_t b0, b1;
                ldsm_x2_trans(bs_frag + k8 * 16 * 144 + nb * 16, b0, b1);
                mma16816(acc[nb], a0, a1, a2, a3, b0, b1);
            }
        }
    }
    __syncthreads();  // all mma done; Cs may alias B buffers now

    // store fragments to Cs
    {
        int fr = wm * 16 + (lane >> 2);
        int fc = wn * 64 + (lane & 3) * 2;
#pragma unroll
        for (int nb = 0; nb < 8; nb++) {
            int c0 = fc + nb * 8;
            Cs[fr * 260 + c0] = acc[nb][0];
            Cs[fr * 260 + c0 + 1] = acc[nb][1];
            Cs[(fr + 8) * 260 + c0] = acc[nb][2];
            Cs[(fr + 8) * 260 + c0 + 1] = acc[nb][3];
        }
    }
    __syncthreads();

    // epilogue: 8 threads per row; each handles 32 cols
    {
        const int er = tid >> 3, es = tid & 7;
        const int gi = r0g + er;
        const float q = g_q[gi];
        const float invZ = g_invZ[gi];
        float vals[32];
        float sum = 0.0f;
#pragma unroll
        for (int c = 0; c < 32; c++) {
            int cc = es * 32 + c;
            float v = (Cs[er * 260 + cc] + q * g_S[cc]) * invZ;
            v = (v > 0.0f) ? v : expm1f(v);
            vals[c] = v;
            sum += v;
        }
#pragma unroll
        for (int o = 1; o < 8; o <<= 1) sum += __shfl_xor_sync(0xffffffffu, sum, o);
        float mean = sum * (1.0f / 256.0f);
        float sq = 0.0f;
#pragma unroll
        for (int c = 0; c < 32; c++) { float dd = vals[c] - mean; sq += dd * dd; }
#pragma unroll
        for (int o = 1; o < 8; o <<= 1) sq += __shfl_xor_sync(0xffffffffu, sq, o);
        float rstd = rsqrtf(sq * (1.0f / 256.0f) + 1e-5f);
#pragma unroll
        for (int c = 0; c < 32; c++) {
            int cc = es * 32 + c;
            float y = (vals[c] - mean) * rstd * lng[cc] + lnb[cc];
            if (residual) y += Xin[(size_t)gi * D + cc];
            Xout[(size_t)gi * D + cc] = y;
        }
    }
}

// ---------------- 6: node logits (8192x64)@(64x5)+b ----------------
__global__ void node_logits_kernel(const float* __restrict__ mid, const float* __restrict__ w2,
                                   const float* __restrict__ b2, float* __restrict__ out) {
    int i = blockIdx.x, t = threadIdx.x;  // 64
    __shared__ float sm[64];
    sm[t] = mid[(size_t)i * 64 + t];
    __syncthreads();
    if (t < 5) {
        float s = b2[t];
#pragma unroll 8
        for (int k = 0; k < 64; k++) s += sm[k] * w2[k * 5 + t];
        out[(size_t)i * 5 + t] = s;
    }
}

// ---------------- 7: deterministic segment pooling ----------------
__global__ void pool_part_kernel(const float* __restrict__ h3, const int* __restrict__ mask) {
    __shared__ float sacc[NG * D];
    int d = threadIdx.x;  // 256
    int b = blockIdx.x;   // 64 blocks x 128 rows
#pragma unroll
    for (int g = 0; g < NG; g++) sacc[g * D + d] = 0.0f;
    __syncthreads();
    int r0 = b * 128, lc = 0;
    for (int r = r0; r < r0 + 128; r++) {
        int g = mask[r];
        sacc[g * D + d] += h3[(size_t)r * D + d];
        if (d < NG && g == d) lc++;
    }
    __syncthreads();
#pragma unroll
    for (int g = 0; g < NG; g++)
        g_gpart[((size_t)b * NG + g) * D + d] = sacc[g * D + d];
    if (d < NG) g_gcntp[b * NG + d] = lc;
}
__global__ void pool_red_kernel() {
    int g = blockIdx.x, d = threadIdx.x;  // 8 x 256
    float s = 0.0f;
    for (int b = 0; b < 64; b++) s += g_gpart[((size_t)b * NG + g) * D + d];
    g_gsum[g * D + d] = s;
    if (d == 0) {
        int c = 0;
        for (int b = 0; b < 64; b++) c += g_gcntp[b * NG + g];
        g_gcnt[g] = (float)c;
    }
}

// ---------------- 8: graph heads ----------------
__global__ void graph_head_kernel(const float* __restrict__ gc_w1, const float* __restrict__ gc_b1,
                                  const float* __restrict__ gc_w2, const float* __restrict__ gc_b2,
                                  const float* __restrict__ rs_w1, const float* __restrict__ rs_b1,
                                  const float* __restrict__ rs_w2, const float* __restrict__ rs_b2,
                                  float* __restrict__ graph_logits, float* __restrict__ risk) {
    __shared__ float ge[D];
    __shared__ float hid[64];
    __shared__ float hid2[32];
    int d = threadIdx.x;  // 256
    for (int g = 0; g < NG; g++) {
        float cnt = fmaxf(g_gcnt[g], 1.0f);
        ge[d] = g_gsum[g * D + d] / cnt;
        __syncthreads();
        if (d < 64) {
            float s = gc_b1[d];
            for (int k = 0; k < D; k++) s += ge[k] * gc_w1[k * 64 + d];
            hid[d] = gelu_exact(s);
        } else if (d < 96) {
            int t = d - 64;
            float s = rs_b1[t];
            for (int k = 0; k < D; k++) s += ge[k] * rs_w1[k * 32 + t];
            hid2[t] = gelu_exact(s);
        }
        __syncthreads();
        if (d < 3) {
            float s = gc_b2[d];
            for (int k = 0; k < 64; k++) s += hid[k] * gc_w2[k * 3 + d];
            graph_logits[g * 3 + d] = s;
        }
        if (d == 3) {
            float s = rs_b2[0];
            for (int k = 0; k < 32; k++) s += hid2[k] * rs_w2[k];
            risk[g] = 1.0f / (1.0f + expf(-s));
        }
        __syncthreads();
    }
}

// ---------------- launch ----------------
extern "C" void kernel_launch(void* const* d_in, const int* in_sizes, int n_in,
                              void* d_out, int out_size) {
    const float* x    = (const float*)d_in[0];
    const float* adj  = (const float*)d_in[1];
    const int*   mask = (const int*)d_in[2];
    const float* W[3]   = {(const float*)d_in[3], (const float*)d_in[5], (const float*)d_in[7]};
    const float* a[3]   = {(const float*)d_in[4], (const float*)d_in[6], (const float*)d_in[8]};
    const float* lng[3] = {(const float*)d_in[9],  (const float*)d_in[11], (const float*)d_in[13]};
    const float* lnb[3] = {(const float*)d_in[10], (const float*)d_in[12], (const float*)d_in[14]};
    const float* nc_w1 = (const float*)d_in[15];
    const float* nc_b1 = (const float*)d_in[16];
    const float* nc_w2 = (const float*)d_in[17];
    const float* nc_b2 = (const float*)d_in[18];
    const float* gc_w1 = (const float*)d_in[19];
    const float* gc_b1 = (const float*)d_in[20];
    const float* gc_w2 = (const float*)d_in[21];
    const float* gc_b2 = (const float*)d_in[22];
    const float* rs_w1 = (const float*)d_in[23];
    const float* rs_b1 = (const float*)d_in[24];
    const float* rs_w2 = (const float*)d_in[25];
    const float* rs_b2 = (const float*)d_in[26];

    float* out = (float*)d_out;
    float* out_node  = out;                 // 8192*5
    float* out_graph = out + 40960;         // 8*3
    float* out_risk  = out + 40984;         // 8
    float* out_h3    = out + 40992;         // 8192*256

    // resolve device-global scratch addresses
    float *pX1, *pX2; void* ph;
    cudaGetSymbolAddress((void**)&pX1, g_X1);
    cudaGetSymbolAddress((void**)&pX2, g_X2);
    cudaGetSymbolAddress(&ph, g_h2);
    float* pmid; cudaGetSymbolAddress((void**)&pmid, g_mid);

    cudaFuncSetAttribute(gat_tile_kernel, cudaFuncAttributeMaxDynamicSharedMemorySize,
                         SM_TOTAL_BYTES);

    build_ell_kernel<<<N_NODES, 256>>>(adj);

    const float* Xprev = x;
    float* Xouts[3] = {pX1, pX2, out_h3};
    for (int L = 0; L < 3; L++) {
        wavec_kernel<<<1, 256>>>(W[L], a[L]);
        s12_kernel<<<N_NODES / 8, 256>>>(Xprev);
        gemm_kernel<0, 1><<<dim3(D / 64, N_NODES / 128), 256>>>(Xprev, W[L], nullptr, ph,
                                                                N_NODES, D, D);
        colsum_part_kernel<<<32, 256>>>();
        colsum_red_kernel<<<1, 256>>>();
        coef_kernel<<<N_NODES / 8, 256>>>();
        gat_tile_kernel<<<128, 512, SM_TOTAL_BYTES>>>(Xprev, lng[L], lnb[L], Xouts[L],
                                                      L > 0 ? 1 : 0);
        Xprev = Xouts[L];
    }

    // node head: mid = gelu(h3 @ nc_w1 + b1); logits = mid @ nc_w2 + b2
    gemm_kernel<1, 0><<<dim3(1, N_NODES / 128), 256>>>(out_h3, nc_w1, nc_b1, pmid,
                                                       N_NODES, 64, D);
    node_logits_kernel<<<N_NODES, 64>>>(pmid, nc_w2, nc_b2, out_node);

    // graph heads
    pool_part_kernel<<<64, 256>>>(out_h3, mask);
    pool_red_kernel<<<NG, 256>>>();
    graph_head_kernel<<<1, 256>>>(gc_w1, gc_b1, gc_w2, gc_b2,
                                  rs_w1, rs_b1, rs_w2, rs_b2,
                                  out_graph, out_risk);
}

// round 10
// speedup vs baseline: 1.9664x; 1.9275x over previous
#include <cuda_runtime.h>
#include <cuda_fp16.h>
#include <math.h>
#include <stdint.h>

#define N_NODES 8192
#define D 256
#define NG 8
#define ELLW 768   // max row degree bound; binomial(8192,0.05) max ~ 490

// ---------------- device scratch (no allocations allowed) ----------------
__device__ unsigned short g_cols[(size_t)N_NODES * ELLW];
__device__ int            g_deg[N_NODES];
__device__ float          g_X1[(size_t)N_NODES * D];
__device__ float          g_X2[(size_t)N_NODES * D];
__device__ __half2        g_Xh[(size_t)N_NODES * (D / 2)];   // fp16 copy of layer input
__device__ __half2        g_Wh[(size_t)D * (D / 2)];         // fp16 copy of W
__device__ __half2        g_h2[(size_t)N_NODES * (D / 2)];   // h = X @ W, fp16 row-major
__device__ float          g_s1[N_NODES];
__device__ float          g_s2[N_NODES];
__device__ float          g_wa[D];
__device__ float          g_wb[D];
__device__ float          g_Spart[32][D];
__device__ float          g_S[D];
__device__ float          g_mid[(size_t)N_NODES * 64];
__device__ float          g_gpart[(size_t)64 * NG * D];
__device__ int            g_gcntp[64 * NG];
__device__ float          g_gsum[NG * D];
__device__ float          g_gcnt[NG];

// ---------------- helpers ----------------
__device__ __forceinline__ float gelu_exact(float x) {
    return 0.5f * x * (1.0f + erff(x * 0.70710678118654752f));
}

__device__ __forceinline__ uint32_t smem_addr(const void* p) {
    return (uint32_t)__cvta_generic_to_shared(p);
}

__device__ __forceinline__ void ldsm_x4(uint32_t addr, uint32_t& r0, uint32_t& r1,
                                        uint32_t& r2, uint32_t& r3) {
    asm volatile("ldmatrix.sync.aligned.m8n8.x4.shared.b16 {%0,%1,%2,%3}, [%4];"
                 : "=r"(r0), "=r"(r1), "=r"(r2), "=r"(r3) : "r"(addr));
}

__device__ __forceinline__ void ldsm_x2_trans(uint32_t addr, uint32_t& r0, uint32_t& r1) {
    asm volatile("ldmatrix.sync.aligned.m8n8.x2.trans.shared.b16 {%0,%1}, [%2];"
                 : "=r"(r0), "=r"(r1) : "r"(addr));
}

__device__ __forceinline__ void mma16816(float* c, uint32_t a0, uint32_t a1, uint32_t a2,
                                         uint32_t a3, uint32_t b0, uint32_t b1) {
    asm volatile(
        "mma.sync.aligned.m16n8k16.row.col.f32.f16.f16.f32 "
        "{%0,%1,%2,%3}, {%4,%5,%6,%7}, {%8,%9}, {%0,%1,%2,%3};"
        : "+f"(c[0]), "+f"(c[1]), "+f"(c[2]), "+f"(c[3])
        : "r"(a0), "r"(a1), "r"(a2), "r"(a3), "r"(b0), "r"(b1));
}

__device__ __forceinline__ float block_sum_256(float v, volatile float* red) {
    int lane = threadIdx.x & 31, w = threadIdx.x >> 5;
#pragma unroll
    for (int o = 16; o > 0; o >>= 1) v += __shfl_down_sync(0xffffffffu, v, o);
    __syncthreads();
    if (lane == 0) red[w] = v;
    __syncthreads();
    float s = 0.0f;
#pragma unroll
    for (int k = 0; k < 8; k++) s += red[k];
    return s;
}

__device__ __forceinline__ float block_max_256(float v, volatile float* red) {
    int lane = threadIdx.x & 31, w = threadIdx.x >> 5;
#pragma unroll
    for (int o = 16; o > 0; o >>= 1) v = fmaxf(v, __shfl_down_sync(0xffffffffu, v, o));
    __syncthreads();
    if (lane == 0) red[w] = v;
    __syncthreads();
    float s = -1e30f;
#pragma unroll
    for (int k = 0; k < 8; k++) s = fmaxf(s, red[k]);
    return s;
}

// ---------------- 0: dense adj -> ELL (deterministic, sorted cols) ----------------
__global__ void build_ell_kernel(const float* __restrict__ adj) {
    int i = blockIdx.x;
    int tid = threadIdx.x;             // 256
    int lane = tid & 31, w = tid >> 5;
    __shared__ int wcnt[8];
    const float* row = adj + (size_t)i * N_NODES;
    int base = 0;
    for (int c0 = 0; c0 < N_NODES; c0 += 256) {
        int c = c0 + tid;
        bool pred = (row[c] != 0.0f);
        unsigned bal = __ballot_sync(0xffffffffu, pred);
        if (lane == 0) wcnt[w] = __popc(bal);
        __syncthreads();
        int off = 0, tot = 0;
#pragma unroll
        for (int k = 0; k < 8; k++) { int v = wcnt[k]; tot += v; if (k < w) off += v; }
        if (pred) {
            int pos = base + off + __popc(bal & ((1u << lane) - 1u));
            if (pos < ELLW) g_cols[(size_t)i * ELLW + pos] = (unsigned short)c;
        }
        base += tot;
        __syncthreads();
    }
    if (tid == 0) g_deg[i] = (base < ELLW) ? base : ELLW;
}

// ---------------- 1: wa = W @ a_top, wb = W @ a_bot ----------------
__global__ void wavec_kernel(const float* __restrict__ W, const float* __restrict__ a) {
    __shared__ float at[D], ab[D];
    int t = threadIdx.x; // 256
    at[t] = a[t];
    ab[t] = a[D + t];
    __syncthreads();
    float s1 = 0.0f, s2 = 0.0f;
    const float* wr = W + (size_t)t * D;
#pragma unroll 8
    for (int c = 0; c < D; c++) { float w = wr[c]; s1 += w * at[c]; s2 += w * ab[c]; }
    g_wa[t] = s1;
    g_wb[t] = s2;
}

// ---------------- 2: s1 = X @ wa, s2 = X @ wb (fp32 exact logit path) ----------------
__global__ void s12_kernel(const float* __restrict__ X) {
    int w = threadIdx.x >> 5, lane = threadIdx.x & 31;
    int i = blockIdx.x * 8 + w;
    const float* xr = X + (size_t)i * D;
    float a1 = 0.0f, a2 = 0.0f;
#pragma unroll
    for (int jj = 0; jj < 8; jj++) {
        int j = jj * 32 + lane;
        float x = xr[j];
        a1 += x * g_wa[j];
        a2 += x * g_wb[j];
    }
#pragma unroll
    for (int o = 16; o > 0; o >>= 1) {
        a1 += __shfl_down_sync(0xffffffffu, a1, o);
        a2 += __shfl_down_sync(0xffffffffu, a2, o);
    }
    if (lane == 0) { g_s1[i] = a1; g_s2[i] = a2; }
}

// ---------------- 2b: fp32 -> fp16 conversion (4 floats per thread) ----------------
__global__ void cvt_half_kernel(const float* __restrict__ A, __half2* __restrict__ O) {
    int idx = blockIdx.x * blockDim.x + threadIdx.x;
    float4 v = reinterpret_cast<const float4*>(A)[idx];
    O[idx * 2]     = __floats2half2_rn(v.x, v.y);
    O[idx * 2 + 1] = __floats2half2_rn(v.z, v.w);
}

// ---------------- 3a: fp16 tensor GEMM  g_h2 = Ah(8192x256) @ Bh(256x256) ----------------
// grid (N/64=4, M/128=64), 256 threads = 8 warps (4 m x 2 n). Fragment math identical
// to the R7 tile kernel (validated correct at rel 1.45e-4).
__global__ __launch_bounds__(256) void h16_gemm_kernel(const __half* __restrict__ Ah,
                                                       const __half* __restrict__ Bh) {
    __shared__ __align__(16) __half As[128 * 72];   // row stride 144 B (conflict-free ldsm)
    __shared__ __align__(16) __half Bs[64 * 72];
    const int tid = threadIdx.x, lane = tid & 31, wid = tid >> 5;
    const int wm = wid >> 1, wn = wid & 1;
    const int m0 = blockIdx.y * 128, n0 = blockIdx.x * 64;
    float acc[2][4][4];
#pragma unroll
    for (int m = 0; m < 2; m++)
#pragma unroll
        for (int n = 0; n < 4; n++)
#pragma unroll
            for (int j = 0; j < 4; j++) acc[m][n][j] = 0.0f;

    const uint32_t as_base = smem_addr(As);
    const uint32_t bs_base = smem_addr(Bs);
    const int ar = tid >> 1, aq = (tid & 1) * 4;   // A: row, uint4 quad base
    const int br = tid >> 2, bq = (tid & 3) * 2;   // B: row, uint4 pair base

    for (int kt = 0; kt < 4; kt++) {
        int k0 = kt * 64;
        {
            const uint4* asrc = reinterpret_cast<const uint4*>(Ah + (size_t)(m0 + ar) * 256 + k0);
            uint4* adst = reinterpret_cast<uint4*>(As + ar * 72);
#pragma unroll
            for (int c = 0; c < 4; c++) adst[aq + c] = asrc[aq + c];
        }
        {
            const uint4* bsrc = reinterpret_cast<const uint4*>(Bh + (size_t)(k0 + br) * 256 + n0);
            uint4* bdst = reinterpret_cast<uint4*>(Bs + br * 72);
            bdst[bq] = bsrc[bq];
            bdst[bq + 1] = bsrc[bq + 1];
        }
        __syncthreads();
#pragma unroll
        for (int k8 = 0; k8 < 4; k8++) {
            uint32_t a0[2], a1[2], a2[2], a3[2];
#pragma unroll
            for (int m = 0; m < 2; m++) {
                uint32_t addr = as_base +
                    (uint32_t)((wm * 32 + m * 16 + (lane & 15)) * 144 + (lane >> 4) * 16 + k8 * 32);
                ldsm_x4(addr, a0[m], a1[m], a2[m], a3[m]);
            }
#pragma unroll
            for (int n8 = 0; n8 < 4; n8++) {
                uint32_t baddr = bs_base +
                    (uint32_t)((k8 * 16 + (lane & 15)) * 144 + (wn * 32 + n8 * 8) * 2);
                uint32_t b0, b1;
                ldsm_x2_trans(baddr, b0, b1);
                mma16816(acc[0][n8], a0[0], a1[0], a2[0], a3[0], b0, b1);
                mma16816(acc[1][n8], a0[1], a1[1], a2[1], a3[1], b0, b1);
            }
        }
        __syncthreads();
    }
    // epilogue: write fp16 h
#pragma unroll
    for (int m = 0; m < 2; m++) {
        int r = m0 + wm * 32 + m * 16 + (lane >> 2);
#pragma unroll
        for (int n8 = 0; n8 < 4; n8++) {
            int cidx = n0 + wn * 32 + n8 * 8 + (lane & 3) * 2;
            g_h2[(size_t)r * 128 + (cidx >> 1)] = __floats2half2_rn(acc[m][n8][0], acc[m][n8][1]);
            g_h2[(size_t)(r + 8) * 128 + (cidx >> 1)] = __floats2half2_rn(acc[m][n8][2], acc[m][n8][3]);
        }
    }
}

// ---------------- 3b: fp32 GEMM (node head only). BM=128,BN=64, 8x4 microtile ----------------
template <int ACT, int OUTH>
__global__ __launch_bounds__(256) void gemm_kernel(const float* __restrict__ A,
                                                   const float* __restrict__ B,
                                                   const float* __restrict__ bias,
                                                   void* __restrict__ C,
                                                   int M, int N, int K) {
    const int BM = 128, BN = 64, BK = 16;
    __shared__ __align__(16) float As[BK][BM];
    __shared__ __align__(16) float Bs[BK][BN];
    int tid = threadIdx.x;  // 256
    int m0 = blockIdx.y * BM, n0 = blockIdx.x * BN;
    int tx = tid & 15, ty = tid >> 4;
    float acc[8][4];
#pragma unroll
    for (int i = 0; i < 8; i++)
#pragma unroll
        for (int j = 0; j < 4; j++) acc[i][j] = 0.0f;

    int ar = tid >> 1;
    int ac = (tid & 1) * 8;
    int br = tid >> 4;
    int bc = (tid & 15) * 4;

    for (int k0 = 0; k0 < K; k0 += BK) {
        {
            const float* ap = &A[(size_t)(m0 + ar) * K + k0 + ac];
            float4 v0 = *reinterpret_cast<const float4*>(ap);
            float4 v1 = *reinterpret_cast<const float4*>(ap + 4);
            As[ac + 0][ar] = v0.x; As[ac + 1][ar] = v0.y;
            As[ac + 2][ar] = v0.z; As[ac + 3][ar] = v0.w;
            As[ac + 4][ar] = v1.x; As[ac + 5][ar] = v1.y;
            As[ac + 6][ar] = v1.z; As[ac + 7][ar] = v1.w;
        }
        {
            float4 v = *reinterpret_cast<const float4*>(&B[(size_t)(k0 + br) * N + n0 + bc]);
            *reinterpret_cast<float4*>(&Bs[br][bc]) = v;
        }
        __syncthreads();
#pragma unroll
        for (int kk = 0; kk < BK; kk++) {
            float4 a0 = *reinterpret_cast<const float4*>(&As[kk][ty * 8]);
            float4 a1 = *reinterpret_cast<const float4*>(&As[kk][ty * 8 + 4]);
            float4 bv = *reinterpret_cast<const float4*>(&Bs[kk][tx * 4]);
            float a8[8] = {a0.x, a0.y, a0.z, a0.w, a1.x, a1.y, a1.z, a1.w};
            float b4[4] = {bv.x, bv.y, bv.z, bv.w};
#pragma unroll
            for (int i = 0; i < 8; i++)
#pragma unroll
                for (int j = 0; j < 4; j++) acc[i][j] += a8[i] * b4[j];
        }
        __syncthreads();
    }
#pragma unroll
    for (int i = 0; i < 8; i++)
#pragma unroll
        for (int j = 0; j < 4; j++) {
            int r = m0 + ty * 8 + i, c = n0 + tx * 4 + j;
            float v = acc[i][j];
            if (ACT == 1) { v += bias[c]; v = gelu_exact(v); }
            if (OUTH) ((__half*)C)[(size_t)r * N + c] = __float2half(v);
            else      ((float*)C)[(size_t)r * N + c] = v;
        }
}

// ---------------- 4: column sum of h ----------------
__global__ void colsum_part_kernel() {
    int d = threadIdx.x, b = blockIdx.x;  // 32 blocks
    const __half* h = reinterpret_cast<const __half*>(g_h2);
    float s = 0.0f;
    int r0 = b * (N_NODES / 32);
    for (int r = r0; r < r0 + (N_NODES / 32); r++) s += __half2float(h[(size_t)r * D + d]);
    g_Spart[b][d] = s;
}
__global__ void colsum_red_kernel() {
    int d = threadIdx.x;
    float s = 0.0f;
#pragma unroll
    for (int b = 0; b < 32; b++) s += g_Spart[b][d];
    g_S[d] = s;
}

// ---------------- 5: GAT row (256 thr, warp-wide row loads) + ELU + LN + residual ----------------
__global__ __launch_bounds__(256) void gat_row2_kernel(const float* __restrict__ Xin,
                                                       const float* __restrict__ lng,
                                                       const float* __restrict__ lnb,
                                                       float* __restrict__ Xout,
                                                       int residual) {
    const int i = blockIdx.x;
    const int t = threadIdx.x, lane = t & 31, w = t >> 5;   // 8 warps
    __shared__ int   cols_sm[ELLW];
    __shared__ float coef_sm[ELLW];
    __shared__ float wpart[8][288];   // stride-9 per lane: idx = lane*9 + f (conflict-free)
    __shared__ float red[8];

    const int deg = g_deg[i];
    const float s1 = g_s1[i];
    const unsigned short* __restrict__ crow = g_cols + (size_t)i * ELLW;

    for (int k = t; k < deg; k += 256) {
        int j = (int)crow[k];
        cols_sm[k] = j;
        coef_sm[k] = g_s2[j];
    }
    __syncthreads();

    // exact row max: m = max(0, lrelu(s1 + max_j s2_j))   (deg==0 -> huge-neg -> m=0)
    float tmax = -1e30f;
    for (int k = t; k < deg; k += 256) tmax = fmaxf(tmax, coef_sm[k]);
    tmax = block_max_256(tmax, red);
    float z0 = s1 + tmax;
    float lr0 = (z0 > 0.0f) ? z0 : 0.2f * z0;
    const float m = fmaxf(lr0, 0.0f);
    const float q = __expf(-m);   // exp(e-m) at every non-edge (e=0)

    float zp = 0.0f;
    for (int k = t; k < deg; k += 256) {
        float z = s1 + coef_sm[k];
        float lr = (z > 0.0f) ? z : 0.2f * z;
        float p = __expf(lr - m);
        zp += p;
        coef_sm[k] = p - q;
    }
    const float Z = block_sum_256(zp, red) + (float)(N_NODES - deg) * q;  // syncs publish coef_sm

    // SpMM: warp w takes edges k = w, w+8, ...; lane owns features [8*lane, 8*lane+8)
    float acc[8];
#pragma unroll
    for (int f = 0; f < 8; f++) acc[f] = 0.0f;
    const uint4* __restrict__ hsrc = reinterpret_cast<const uint4*>(g_h2);
#pragma unroll 4
    for (int k = w; k < deg; k += 8) {
        float c = coef_sm[k];             // broadcast LDS
        int j = cols_sm[k];               // broadcast LDS
        uint4 v = __ldg(&hsrc[((size_t)j << 5) + lane]);   // whole row per warp, LDG.128
        const __half2* hv = reinterpret_cast<const __half2*>(&v);
        float2 f0 = __half22float2(hv[0]);
        float2 f1 = __half22float2(hv[1]);
        float2 f2 = __half22float2(hv[2]);
        float2 f3 = __half22float2(hv[3]);
        acc[0] += c * f0.x; acc[1] += c * f0.y;
        acc[2] += c * f1.x; acc[3] += c * f1.y;
        acc[4] += c * f2.x; acc[5] += c * f2.y;
        acc[6] += c * f3.x; acc[7] += c * f3.y;
    }
#pragma unroll
    for (int f = 0; f < 8; f++) wpart[w][lane * 9 + f] = acc[f];   // conflict-free (9l+f mod 32)
    __syncthreads();

    // thread t owns feature t
    float v;
    {
        int idx = (t >> 3) * 9 + (t & 7);
        float s = 0.0f;
#pragma unroll
        for (int ww = 0; ww < 8; ww++) s += wpart[ww][idx];
        v = (s + q * g_S[t]) / Z;
        v = (v > 0.0f) ? v : expm1f(v);
    }

    // LayerNorm over 256 features (biased var, eps 1e-5) + residual
    float sum = block_sum_256(v, red);
    float mean = sum * (1.0f / 256.0f);
    float d = v - mean;
    float sq = block_sum_256(d * d, red);
    float rstd = rsqrtf(sq * (1.0f / 256.0f) + 1e-5f);
    float y = d * rstd * lng[t] + lnb[t];
    if (residual) y += Xin[(size_t)i * D + t];
    Xout[(size_t)i * D + t] = y;
}

// ---------------- 6: node logits (8192x64)@(64x5)+b ----------------
__global__ void node_logits_kernel(const float* __restrict__ mid, const float* __restrict__ w2,
                                   const float* __restrict__ b2, float* __restrict__ out) {
    int i = blockIdx.x, t = threadIdx.x;  // 64
    __shared__ float sm[64];
    sm[t] = mid[(size_t)i * 64 + t];
    __syncthreads();
    if (t < 5) {
        float s = b2[t];
#pragma unroll 8
        for (int k = 0; k < 64; k++) s += sm[k] * w2[k * 5 + t];
        out[(size_t)i * 5 + t] = s;
    }
}

// ---------------- 7: deterministic segment pooling ----------------
__global__ void pool_part_kernel(const float* __restrict__ h3, const int* __restrict__ mask) {
    __shared__ float sacc[NG * D];
    int d = threadIdx.x;  // 256
    int b = blockIdx.x;   // 64 blocks x 128 rows
#pragma unroll
    for (int g = 0; g < NG; g++) sacc[g * D + d] = 0.0f;
    __syncthreads();
    int r0 = b * 128, lc = 0;
    for (int r = r0; r < r0 + 128; r++) {
        int g = mask[r];
        sacc[g * D + d] += h3[(size_t)r * D + d];
        if (d < NG && g == d) lc++;
    }
    __syncthreads();
#pragma unroll
    for (int g = 0; g < NG; g++)
        g_gpart[((size_t)b * NG + g) * D + d] = sacc[g * D + d];
    if (d < NG) g_gcntp[b * NG + d] = lc;
}
__global__ void pool_red_kernel() {
    int g = blockIdx.x, d = threadIdx.x;  // 8 x 256
    float s = 0.0f;
    for (int b = 0; b < 64; b++) s += g_gpart[((size_t)b * NG + g) * D + d];
    g_gsum[g * D + d] = s;
    if (d == 0) {
        int c = 0;
        for (int b = 0; b < 64; b++) c += g_gcntp[b * NG + g];
        g_gcnt[g] = (float)c;
    }
}

// ---------------- 8: graph heads ----------------
__global__ void graph_head_kernel(const float* __restrict__ gc_w1, const float* __restrict__ gc_b1,
                                  const float* __restrict__ gc_w2, const float* __restrict__ gc_b2,
                                  const float* __restrict__ rs_w1, const float* __restrict__ rs_b1,
                                  const float* __restrict__ rs_w2, const float* __restrict__ rs_b2,
                                  float* __restrict__ graph_logits, float* __restrict__ risk) {
    __shared__ float ge[D];
    __shared__ float hid[64];
    __shared__ float hid2[32];
    int d = threadIdx.x;  // 256
    for (int g = 0; g < NG; g++) {
        float cnt = fmaxf(g_gcnt[g], 1.0f);
        ge[d] = g_gsum[g * D + d] / cnt;
        __syncthreads();
        if (d < 64) {
            float s = gc_b1[d];
            for (int k = 0; k < D; k++) s += ge[k] * gc_w1[k * 64 + d];
            hid[d] = gelu_exact(s);
        } else if (d < 96) {
            int t = d - 64;
            float s = rs_b1[t];
            for (int k = 0; k < D; k++) s += ge[k] * rs_w1[k * 32 + t];
            hid2[t] = gelu_exact(s);
        }
        __syncthreads();
        if (d < 3) {
            float s = gc_b2[d];
            for (int k = 0; k < 64; k++) s += hid[k] * gc_w2[k * 3 + d];
            graph_logits[g * 3 + d] = s;
        }
        if (d == 3) {
            float s = rs_b2[0];
            for (int k = 0; k < 32; k++) s += hid2[k] * rs_w2[k];
            risk[g] = 1.0f / (1.0f + expf(-s));
        }
        __syncthreads();
    }
}

// ---------------- launch ----------------
extern "C" void kernel_launch(void* const* d_in, const int* in_sizes, int n_in,
                              void* d_out, int out_size) {
    const float* x    = (const float*)d_in[0];
    const float* adj  = (const float*)d_in[1];
    const int*   mask = (const int*)d_in[2];
    const float* W[3]   = {(const float*)d_in[3], (const float*)d_in[5], (const float*)d_in[7]};
    const float* a[3]   = {(const float*)d_in[4], (const float*)d_in[6], (const float*)d_in[8]};
    const float* lng[3] = {(const float*)d_in[9],  (const float*)d_in[11], (const float*)d_in[13]};
    const float* lnb[3] = {(const float*)d_in[10], (const float*)d_in[12], (const float*)d_in[14]};
    const float* nc_w1 = (const float*)d_in[15];
    const float* nc_b1 = (const float*)d_in[16];
    const float* nc_w2 = (const float*)d_in[17];
    const float* nc_b2 = (const float*)d_in[18];
    const float* gc_w1 = (const float*)d_in[19];
    const float* gc_b1 = (const float*)d_in[20];
    const float* gc_w2 = (const float*)d_in[21];
    const float* gc_b2 = (const float*)d_in[22];
    const float* rs_w1 = (const float*)d_in[23];
    const float* rs_b1 = (const float*)d_in[24];
    const float* rs_w2 = (const float*)d_in[25];
    const float* rs_b2 = (const float*)d_in[26];

    float* out = (float*)d_out;
    float* out_node  = out;                 // 8192*5
    float* out_graph = out + 40960;         // 8*3
    float* out_risk  = out + 40984;         // 8
    float* out_h3    = out + 40992;         // 8192*256

    // resolve device-global scratch addresses
    float *pX1, *pX2;
    cudaGetSymbolAddress((void**)&pX1, g_X1);
    cudaGetSymbolAddress((void**)&pX2, g_X2);
    void *pXh, *pWh;
    cudaGetSymbolAddress(&pXh, g_Xh);
    cudaGetSymbolAddress(&pWh, g_Wh);
    float* pmid; cudaGetSymbolAddress((void**)&pmid, g_mid);

    build_ell_kernel<<<N_NODES, 256>>>(adj);

    const float* Xprev = x;
    float* Xouts[3] = {pX1, pX2, out_h3};
    for (int L = 0; L < 3; L++) {
        wavec_kernel<<<1, 256>>>(W[L], a[L]);
        s12_kernel<<<N_NODES / 8, 256>>>(Xprev);
        cvt_half_kernel<<<2048, 256>>>(Xprev, (__half2*)pXh);
        cvt_half_kernel<<<64, 256>>>(W[L], (__half2*)pWh);
        h16_gemm_kernel<<<dim3(4, 64), 256>>>((const __half*)pXh, (const __half*)pWh);
        colsum_part_kernel<<<32, 256>>>();
        colsum_red_kernel<<<1, 256>>>();
        gat_row2_kernel<<<N_NODES, 256>>>(Xprev, lng[L], lnb[L], Xouts[L], L > 0 ? 1 : 0);
        Xprev = Xouts[L];
    }

    // node head: mid = gelu(h3 @ nc_w1 + b1); logits = mid @ nc_w2 + b2
    gemm_kernel<1, 0><<<dim3(1, N_NODES / 128), 256>>>(out_h3, nc_w1, nc_b1, pmid,
                                                       N_NODES, 64, D);
    node_logits_kernel<<<N_NODES, 64>>>(pmid, nc_w2, nc_b2, out_node);

    // graph heads
    pool_part_kernel<<<64, 256>>>(out_h3, mask);
    pool_red_kernel<<<NG, 256>>>();
    graph_head_kernel<<<1, 256>>>(gc_w1, gc_b1, gc_w2, gc_b2,
                                  rs_w1, rs_b1, rs_w2, rs_b2,
                                  out_graph, out_risk);
}